// round 16
// baseline (speedup 1.0000x reference)
#include <cuda_runtime.h>
#include <cuda_fp16.h>
#include <cstdint>
#include <math.h>

// Problem dims (fixed)
static constexpr int DIM_N = 4096;  // samples
static constexpr int DIM_D = 512;   // feature dim
static constexpr int DIM_M = 4096;  // M columns
static constexpr int DIM_K = 2048;  // centroids
static constexpr int ZSPLIT = 16;   // split-K factor for S = X^T X
static constexpr int DIM_CM = DIM_K + DIM_M;  // stacked [C; Mt] rows = 6144

// ---------------- scratch (device globals; allocation-free) ----------------
__device__ __half g_Xt_hi[DIM_D * DIM_N];    // X^T  [512, 4096]
__device__ __half g_CM_hi[DIM_CM * DIM_D];   // [C; M^T]  [6144, 512]
__device__ __half g_S_hi[DIM_D * DIM_D];     // S    [512, 512]
__device__ __half g_U_hi[DIM_K * DIM_D];     // U = C@S  [2048, 512]
__device__ float g_Spart[ZSPLIT * DIM_D * DIM_D];   // split-K partials (upper tiles)
__device__ float g_dotp[4 * DIM_CM];                // per-col-band dot partials

// ---------------------------- warp-MMA helpers ------------------------------
__device__ __forceinline__ uint32_t smem_u32(const void* p) {
    uint32_t a;
    asm("{ .reg .u64 t; cvta.to.shared.u64 t, %1; cvt.u32.u64 %0, t; }" : "=r"(a) : "l"(p));
    return a;
}
__device__ __forceinline__ void ldm_x4(uint32_t* r, uint32_t addr) {
    asm volatile("ldmatrix.sync.aligned.m8n8.x4.shared.b16 {%0,%1,%2,%3}, [%4];"
                 : "=r"(r[0]), "=r"(r[1]), "=r"(r[2]), "=r"(r[3]) : "r"(addr));
}
__device__ __forceinline__ void mma_f16(float* c, const uint32_t* a, const uint32_t* b) {
    asm volatile("mma.sync.aligned.m16n8k16.row.col.f32.f16.f16.f32 "
                 "{%0,%1,%2,%3}, {%4,%5,%6,%7}, {%8,%9}, {%0,%1,%2,%3};"
                 : "+f"(c[0]), "+f"(c[1]), "+f"(c[2]), "+f"(c[3])
                 : "r"(a[0]), "r"(a[1]), "r"(a[2]), "r"(a[3]), "r"(b[0]), "r"(b[1]));
}
#define CP_ASYNC16(dst, src) \
    asm volatile("cp.async.cg.shared.global [%0], [%1], 16;" :: "r"(dst), "l"(src))
#define CP_COMMIT() asm volatile("cp.async.commit_group;" ::: "memory")
#define CP_WAIT1()  asm volatile("cp.async.wait_group 1;" ::: "memory")
#define CP_WAIT0()  asm volatile("cp.async.wait_group 0;" ::: "memory")

// 128B-row smem layout with XOR swizzle: 16B chunk column ^= (row & 7).
__device__ __forceinline__ uint32_t swz(uint32_t row, uint32_t col) {
    return row * 128 + (col ^ ((row & 7) << 4));
}

// ---------------------------------------------------------------------------
// Single-product fp16 GEMM via mma.sync:  G[i,j] = sum_k Ahi[i,k] * Bhi[j,k]
// CTA tile 128x128, K-slab 64, 256 threads = 8 warps (2x4), warp tile 64x32.
// 3-stage cp.async pipeline, 32KB stages (96KB smem, 2 CTA/SM).
// MODE 1: fused distance epilogue using raw dotp partials:
//         radd = sum_z dotp[z*CM + row], cadd = sum_z dotp[z*CM + K + col];
//         out = sqrt(max(cadd - 2g + radd, 0)).
// MODE 2: UT mode (Ktot==No==512): fp16 G -> Uhi (rows < DIM_K) + per-CTA-band
//         dot partials dotp[bx*DIM_CM+row] = sum_{c in band} Ahi[row,c]*G[row,c].
// MODE 3: symmetric-S split-K: blockIdx.x in [0,10) maps to upper-tri tile
//         pair (by<=bx) of the 4x4 tile grid; writes fp32 Spart slice.
// ---------------------------------------------------------------------------
static constexpr int TILE_BYTES = 128 * 128;           // 16384
static constexpr int STAGE_BYTES = 2 * TILE_BYTES;     // 32768
static constexpr int GEMM_SMEM = 3 * STAGE_BYTES;      // 98304

template <int MODE>
__global__ __launch_bounds__(256, 2)
void f16s_gemm(const __half* __restrict__ Ahi,
               const __half* __restrict__ Bhi,
               float* __restrict__ Cout,
               int No, int Ktot, int kspan, size_t zstride,
               __half* __restrict__ Uhi, float* __restrict__ dotp)
{
    extern __shared__ __align__(128) unsigned char smem[];
    const uint32_t sbase = smem_u32(smem);
    const uint32_t OFF_AHI = 0, OFF_BHI = TILE_BYTES;

    const int tid = threadIdx.x;
    const int wid = tid >> 5;
    const int lane = tid & 31;
    const int warp_m = wid >> 2;     // 0..1 -> 64 rows each
    const int warp_n = wid & 3;      // 0..3 -> 32 cols each

    int bxt, byt;
    if (MODE == 3) {
        // upper-triangular tile pairs of a 4x4 grid: (by,bx), by<=bx
        const int p = blockIdx.x;
        byt = (p < 4) ? 0 : (p < 7) ? 1 : (p < 9) ? 2 : 3;
        bxt = p - ((byt == 0) ? 0 : (byt == 1) ? 3 : (byt == 2) ? 5 : 6);
    } else {
        bxt = blockIdx.x;
        byt = blockIdx.y;
    }
    const int rowA0 = byt * 128;
    const int rowB0 = bxt * 128;
    const int kz = blockIdx.z * kspan;
    const int nslabs = kspan / 64;
    if (MODE == 3) Cout += (size_t)blockIdx.z * zstride;

    float acc[4][4][4];
#pragma unroll
    for (int i = 0; i < 4; i++)
#pragma unroll
        for (int j = 0; j < 4; j++)
#pragma unroll
            for (int v = 0; v < 4; v++) acc[i][j][v] = 0.0f;

    // ldmatrix lane addressing (k-invariant parts)
    const int a_row = warp_m * 64 + (lane & 15);
    const uint32_t a_coff = (uint32_t)((lane >> 4) << 4);
    const int b_row = warp_n * 32 + ((lane >> 4) << 3) + (lane & 7);
    const uint32_t b_coff = (uint32_t)(((lane >> 3) & 1) << 4);

    auto load_slab = [&](int slab, int stage) {
        const int kbase = kz + slab * 64;
        const uint32_t st = (uint32_t)stage * STAGE_BYTES;
#pragma unroll
        for (int i = 0; i < 4; i++) {
            const int idx = tid + i * 256;       // 0..1023
            const int r = idx >> 3;
            const int c = idx & 7;               // 16B chunk within 128B row
            const size_t aoff = (size_t)(rowA0 + r) * Ktot + kbase + c * 8;
            const size_t boff = (size_t)(rowB0 + r) * Ktot + kbase + c * 8;
            const uint32_t so = st + swz((uint32_t)r, (uint32_t)(c * 16));
            CP_ASYNC16(sbase + OFF_AHI + so, Ahi + aoff);
            CP_ASYNC16(sbase + OFF_BHI + so, Bhi + boff);
        }
    };

    // 3-stage pipeline: prefetch distance 2.
    load_slab(0, 0); CP_COMMIT();
    if (nslabs > 1) { load_slab(1, 1); CP_COMMIT(); }

    for (int slab = 0; slab < nslabs; slab++) {
        if (slab + 2 < nslabs) { CP_WAIT1(); } else { CP_WAIT0(); }
        __syncthreads();          // slab data visible; stage (slab+2)%3 free
        if (slab + 2 < nslabs) {
            load_slab(slab + 2, (slab + 2) % 3);
            CP_COMMIT();
        }

        const uint32_t st = (uint32_t)(slab % 3) * STAGE_BYTES;
#pragma unroll
        for (int kk = 0; kk < 4; kk++) {         // four k16 steps per slab
            const uint32_t kcol = kk * 32;
            uint32_t a_hi[4][4], b_hi[2][4];
#pragma unroll
            for (int mi = 0; mi < 4; mi++) {
                const uint32_t ar = st + swz((uint32_t)(a_row + mi * 16), kcol + a_coff);
                ldm_x4(a_hi[mi], sbase + OFF_AHI + ar);
            }
#pragma unroll
            for (int p = 0; p < 2; p++) {        // nj pairs {0,1}, {2,3}
                const uint32_t br = st + swz((uint32_t)(b_row + p * 16), kcol + b_coff);
                ldm_x4(b_hi[p], sbase + OFF_BHI + br);
            }
#pragma unroll
            for (int mi = 0; mi < 4; mi++)
#pragma unroll
                for (int nj = 0; nj < 4; nj++)
                    mma_f16(acc[mi][nj], a_hi[mi], &b_hi[nj >> 1][(nj & 1) * 2]);
        }
    }

    // ---------------- epilogue ----------------
    // c-frag layout: c0,c1 -> row lane/4, cols (lane%4)*2+{0,1}; c2,c3 -> row+8
    const int er0 = rowA0 + warp_m * 64 + (lane >> 2);
    const int ec0 = rowB0 + warp_n * 32 + (lane & 3) * 2;

    if (MODE == 2) {
        __syncthreads();                          // mainloop smem reuse
        float* sm_dot = (float*)smem;             // [128 rows][4 warp_n]
#pragma unroll
        for (int mi = 0; mi < 4; mi++) {
#pragma unroll
            for (int half = 0; half < 2; half++) {
                const int row = er0 + mi * 16 + half * 8;
                float rs = 0.0f;
#pragma unroll
                for (int nj = 0; nj < 4; nj++) {
                    const int col = ec0 + nj * 8;
                    float2 v;
                    v.x = acc[mi][nj][half * 2 + 0];
                    v.y = acc[mi][nj][half * 2 + 1];
                    const size_t o = (size_t)row * Ktot + col;
                    const float ax = __half2float(Ahi[o]);
                    const float ay = __half2float(Ahi[o + 1]);
                    rs = fmaf(ax, v.x, rs);
                    rs = fmaf(ay, v.y, rs);
                    if (row < DIM_K) {            // write U (fp16 hi only)
                        __half2 h2;
                        h2.x = __float2half_rn(v.x);
                        h2.y = __float2half_rn(v.y);
                        *(__half2*)(Uhi + (size_t)row * DIM_D + col) = h2;
                    }
                }
                rs += __shfl_xor_sync(0xFFFFFFFFu, rs, 1);
                rs += __shfl_xor_sync(0xFFFFFFFFu, rs, 2);
                if ((lane & 3) == 0) {
                    const int lr = warp_m * 64 + mi * 16 + half * 8 + (lane >> 2);
                    sm_dot[lr * 4 + warp_n] = rs;
                }
            }
        }
        __syncthreads();
        if (tid < 128) {
            const float s = sm_dot[tid * 4] + sm_dot[tid * 4 + 1]
                          + sm_dot[tid * 4 + 2] + sm_dot[tid * 4 + 3];
            dotp[(size_t)blockIdx.x * DIM_CM + rowA0 + tid] = s;
        }
        return;
    }

#pragma unroll
    for (int mi = 0; mi < 4; mi++) {
#pragma unroll
        for (int half = 0; half < 2; half++) {
            const int row = er0 + mi * 16 + half * 8;
            float radd = 0.0f;
            if (MODE == 1) {
                radd = dotp[row] + dotp[DIM_CM + row]
                     + dotp[2 * DIM_CM + row] + dotp[3 * DIM_CM + row];
            }
#pragma unroll
            for (int nj = 0; nj < 4; nj++) {
                const int col = ec0 + nj * 8;
                float2 v;
                v.x = acc[mi][nj][half * 2 + 0];
                v.y = acc[mi][nj][half * 2 + 1];
                if (MODE == 1) {
                    const int ci = DIM_K + col;
                    const float cx = dotp[ci] + dotp[DIM_CM + ci]
                                   + dotp[2 * DIM_CM + ci] + dotp[3 * DIM_CM + ci];
                    const float cy = dotp[ci + 1] + dotp[DIM_CM + ci + 1]
                                   + dotp[2 * DIM_CM + ci + 1] + dotp[3 * DIM_CM + ci + 1];
                    v.x = sqrtf(fmaxf(cx - 2.0f * v.x + radd, 0.0f));
                    v.y = sqrtf(fmaxf(cy - 2.0f * v.y + radd, 0.0f));
                }
                *(float2*)(Cout + (size_t)row * No + col) = v;
            }
        }
    }
}

// ------------------------- conversion / small kernels -----------------------
__global__ void half_kernel(const float* __restrict__ in,
                            __half* __restrict__ hi, int n)
{
    const int i = blockIdx.x * blockDim.x + threadIdx.x;
    if (i >= n) return;
    hi[i] = __float2half_rn(in[i]);
}

// in [R,C] fp32 -> hi [C,R] fp16 (transpose)
__global__ void half_transpose_kernel(const float* __restrict__ in,
                                      __half* __restrict__ hi, int R, int C)
{
    __shared__ float t[32][33];
    const int x = blockIdx.x * 32 + threadIdx.x;
    const int y0 = blockIdx.y * 32;
#pragma unroll
    for (int j = 0; j < 32; j += 8)
        t[threadIdx.y + j][threadIdx.x] = in[(size_t)(y0 + threadIdx.y + j) * C + x];
    __syncthreads();
#pragma unroll
    for (int j = 0; j < 32; j += 8) {
        const int c = blockIdx.x * 32 + threadIdx.y + j;
        const int r = y0 + threadIdx.x;
        hi[(size_t)c * R + r] = __float2half_rn(t[threadIdx.x][threadIdx.y + j]);
    }
}

// sum split-K partials of S -> fp16 hi, mirroring lower-tri tiles from upper.
__global__ void reduce_split_kernel(const float* __restrict__ part,
                                    __half* __restrict__ hi, int n)
{
    const int i = blockIdx.x * blockDim.x + threadIdx.x;
    if (i >= n) return;
    const int r = i >> 9;            // row in [0,512)
    const int c = i & 511;           // col
    // only tiles with rowtile <= coltile were computed
    const int src = ((r >> 7) > (c >> 7)) ? (c * DIM_D + r) : i;
    float acc = 0.0f;
#pragma unroll
    for (int z = 0; z < ZSPLIT; z++) acc += part[src + (size_t)z * n];
    hi[i] = __float2half_rn(acc);
}

// --------------------------------- launch ----------------------------------
extern "C" void kernel_launch(void* const* d_in, const int* in_sizes, int n_in,
                              void* d_out, int out_size)
{
    const float* X = (const float*)d_in[0];  // [4096, 512]
    const float* M = (const float*)d_in[1];  // [512, 4096]
    const float* C = (const float*)d_in[2];  // [2048, 512]
    float* out = (float*)d_out;              // [2048, 4096]

    static bool attr_done = false;
    if (!attr_done) {
        cudaFuncSetAttribute(f16s_gemm<1>, cudaFuncAttributeMaxDynamicSharedMemorySize, GEMM_SMEM);
        cudaFuncSetAttribute(f16s_gemm<2>, cudaFuncAttributeMaxDynamicSharedMemorySize, GEMM_SMEM);
        cudaFuncSetAttribute(f16s_gemm<3>, cudaFuncAttributeMaxDynamicSharedMemorySize, GEMM_SMEM);
        attr_done = true;
    }

    __half *Xt_hi, *CM_hi, *S_hi, *U_hi;
    float *Spart, *dotp;
    cudaGetSymbolAddress((void**)&Xt_hi, g_Xt_hi);
    cudaGetSymbolAddress((void**)&CM_hi, g_CM_hi);
    cudaGetSymbolAddress((void**)&S_hi,  g_S_hi);
    cudaGetSymbolAddress((void**)&U_hi,  g_U_hi);
    cudaGetSymbolAddress((void**)&Spart, g_Spart);
    cudaGetSymbolAddress((void**)&dotp,  g_dotp);

    __half* Mt_hi = CM_hi + (size_t)DIM_K * DIM_D;  // rows 2048..6143

    // 1) fp16 conversions: Xt [512,4096]; CM = [C; M^T] [6144,512]
    half_transpose_kernel<<<dim3(DIM_D / 32, DIM_N / 32), dim3(32, 8)>>>(X, Xt_hi, DIM_N, DIM_D);
    half_kernel<<<(DIM_K * DIM_D) / 256, 256>>>(C, CM_hi, DIM_K * DIM_D);
    half_transpose_kernel<<<dim3(DIM_M / 32, DIM_D / 32), dim3(32, 8)>>>(M, Mt_hi, DIM_D, DIM_M);

    // 2) S = Xt_hi @ Xt_hi^T (symmetric: 10 upper tile pairs), split-K=16
    f16s_gemm<3><<<dim3(10, 1, ZSPLIT), 256, GEMM_SMEM>>>(
        Xt_hi, Xt_hi, Spart,
        DIM_D, DIM_N, DIM_N / ZSPLIT, (size_t)DIM_D * DIM_D,
        nullptr, nullptr);
    reduce_split_kernel<<<(DIM_D * DIM_D) / 256, 256>>>(Spart, S_hi, DIM_D * DIM_D);

    // 3) UT = CM_hi @ S_hi  (MODE2: writes U_hi for C rows + dot partials)
    f16s_gemm<2><<<dim3(DIM_D / 128, DIM_CM / 128, 1), 256, GEMM_SMEM>>>(
        CM_hi, S_hi, nullptr, DIM_D, DIM_D, DIM_D, 0,
        U_hi, dotp);

    // 4) out[k,m] = sqrt(max(xm2[m] - 2*(U_hi @ Mt_hi^T)[k,m] + xc2[k], 0))
    //    (xc2/xm2 summed from dotp partials inside the epilogue)
    f16s_gemm<1><<<dim3(DIM_M / 128, DIM_K / 128, 1), 256, GEMM_SMEM>>>(
        U_hi, Mt_hi, out, DIM_M, DIM_D, DIM_D, 0,
        nullptr, dotp);
}

// round 17
// speedup vs baseline: 1.1913x; 1.1913x over previous
#include <cuda_runtime.h>
#include <cuda_fp16.h>
#include <cstdint>
#include <math.h>

// Problem dims (fixed)
static constexpr int DIM_N = 4096;  // samples
static constexpr int DIM_D = 512;   // feature dim
static constexpr int DIM_M = 4096;  // M columns
static constexpr int DIM_K = 2048;  // centroids
static constexpr int ZSPLIT = 8;    // split-K factor for S = X^T X
static constexpr int DIM_CM = DIM_K + DIM_M;  // stacked [C; Mt] rows = 6144

// ---------------- scratch (device globals; allocation-free) ----------------
__device__ __half g_Xt_hi[DIM_D * DIM_N];    // X^T  [512, 4096]
__device__ __half g_CM_hi[DIM_CM * DIM_D];   // [C; M^T]  [6144, 512]
__device__ __half g_S_hi[DIM_D * DIM_D];     // S    [512, 512]
__device__ __half g_U_hi[DIM_K * DIM_D];     // U = C@S  [2048, 512]
__device__ float g_Spart[ZSPLIT * DIM_D * DIM_D];   // split-K partials
__device__ float g_dotp[4 * DIM_CM];                // per-col-band dot partials
__device__ float g_xm2[DIM_M];
__device__ float g_xc2[DIM_K];

// ---------------------------- warp-MMA helpers ------------------------------
__device__ __forceinline__ uint32_t smem_u32(const void* p) {
    uint32_t a;
    asm("{ .reg .u64 t; cvta.to.shared.u64 t, %1; cvt.u32.u64 %0, t; }" : "=r"(a) : "l"(p));
    return a;
}
__device__ __forceinline__ void ldm_x4(uint32_t* r, uint32_t addr) {
    asm volatile("ldmatrix.sync.aligned.m8n8.x4.shared.b16 {%0,%1,%2,%3}, [%4];"
                 : "=r"(r[0]), "=r"(r[1]), "=r"(r[2]), "=r"(r[3]) : "r"(addr));
}
__device__ __forceinline__ void mma_f16(float* c, const uint32_t* a, const uint32_t* b) {
    asm volatile("mma.sync.aligned.m16n8k16.row.col.f32.f16.f16.f32 "
                 "{%0,%1,%2,%3}, {%4,%5,%6,%7}, {%8,%9}, {%0,%1,%2,%3};"
                 : "+f"(c[0]), "+f"(c[1]), "+f"(c[2]), "+f"(c[3])
                 : "r"(a[0]), "r"(a[1]), "r"(a[2]), "r"(a[3]), "r"(b[0]), "r"(b[1]));
}
#define CP_ASYNC16(dst, src) \
    asm volatile("cp.async.cg.shared.global [%0], [%1], 16;" :: "r"(dst), "l"(src))
#define CP_COMMIT() asm volatile("cp.async.commit_group;" ::: "memory")
#define CP_WAIT1()  asm volatile("cp.async.wait_group 1;" ::: "memory")
#define CP_WAIT0()  asm volatile("cp.async.wait_group 0;" ::: "memory")

// 128B-row smem layout with XOR swizzle: 16B chunk column ^= (row & 7).
__device__ __forceinline__ uint32_t swz(uint32_t row, uint32_t col) {
    return row * 128 + (col ^ ((row & 7) << 4));
}

// ---------------------------------------------------------------------------
// Single-product fp16 GEMM via mma.sync:  G[i,j] = sum_k Ahi[i,k] * Bhi[j,k]
// A [Mo,Ktot] K-major fp16, B [No,Ktot] K-major fp16.
// CTA tile 128x128, K-slab 64, 256 threads = 8 warps (2x4), warp tile 64x32.
// 3-stage cp.async pipeline, 32KB stages (96KB smem, 2 CTA/SM).
// MODE 0: write fp32 Cout (with z-split offsets).
// MODE 1: fused distance epilogue: out = sqrt(max(colAdd[c] - 2g + rowAdd[r],0)).
// MODE 2: UT mode (Ktot==No==512): fp16 G -> Uhi (rows < DIM_K) + per-CTA-band
//         dot partials dotp[bx*DIM_CM+row] = sum_{c in band} Ahi[row,c]*G[row,c].
// ---------------------------------------------------------------------------
static constexpr int TILE_BYTES = 128 * 128;           // 16384
static constexpr int STAGE_BYTES = 2 * TILE_BYTES;     // 32768
static constexpr int GEMM_SMEM = 3 * STAGE_BYTES;      // 98304

template <int MODE>
__global__ __launch_bounds__(256, 2)
void f16s_gemm(const __half* __restrict__ Ahi,
               const __half* __restrict__ Bhi,
               float* __restrict__ Cout,
               int No, int Ktot, int kspan, size_t zstride,
               const float* __restrict__ rowAdd, const float* __restrict__ colAdd,
               __half* __restrict__ Uhi, float* __restrict__ dotp)
{
    extern __shared__ __align__(128) unsigned char smem[];
    const uint32_t sbase = smem_u32(smem);
    const uint32_t OFF_AHI = 0, OFF_BHI = TILE_BYTES;

    const int tid = threadIdx.x;
    const int wid = tid >> 5;
    const int lane = tid & 31;
    const int warp_m = wid >> 2;     // 0..1 -> 64 rows each
    const int warp_n = wid & 3;      // 0..3 -> 32 cols each
    const int rowA0 = blockIdx.y * 128;
    const int rowB0 = blockIdx.x * 128;
    const int kz = blockIdx.z * kspan;
    const int nslabs = kspan / 64;
    if (MODE == 0) Cout += (size_t)blockIdx.z * zstride;

    float acc[4][4][4];
#pragma unroll
    for (int i = 0; i < 4; i++)
#pragma unroll
        for (int j = 0; j < 4; j++)
#pragma unroll
            for (int v = 0; v < 4; v++) acc[i][j][v] = 0.0f;

    // ldmatrix lane addressing (k-invariant parts)
    const int a_row = warp_m * 64 + (lane & 15);
    const uint32_t a_coff = (uint32_t)((lane >> 4) << 4);
    const int b_row = warp_n * 32 + ((lane >> 4) << 3) + (lane & 7);
    const uint32_t b_coff = (uint32_t)(((lane >> 3) & 1) << 4);

    auto load_slab = [&](int slab, int stage) {
        const int kbase = kz + slab * 64;
        const uint32_t st = (uint32_t)stage * STAGE_BYTES;
#pragma unroll
        for (int i = 0; i < 4; i++) {
            const int idx = tid + i * 256;       // 0..1023
            const int r = idx >> 3;
            const int c = idx & 7;               // 16B chunk within 128B row
            const size_t aoff = (size_t)(rowA0 + r) * Ktot + kbase + c * 8;
            const size_t boff = (size_t)(rowB0 + r) * Ktot + kbase + c * 8;
            const uint32_t so = st + swz((uint32_t)r, (uint32_t)(c * 16));
            CP_ASYNC16(sbase + OFF_AHI + so, Ahi + aoff);
            CP_ASYNC16(sbase + OFF_BHI + so, Bhi + boff);
        }
    };

    // 3-stage pipeline: prefetch distance 2.
    load_slab(0, 0); CP_COMMIT();
    if (nslabs > 1) { load_slab(1, 1); CP_COMMIT(); }

    for (int slab = 0; slab < nslabs; slab++) {
        if (slab + 2 < nslabs) { CP_WAIT1(); } else { CP_WAIT0(); }
        __syncthreads();          // slab data visible; stage (slab+2)%3 free
        if (slab + 2 < nslabs) {
            load_slab(slab + 2, (slab + 2) % 3);
            CP_COMMIT();
        }

        const uint32_t st = (uint32_t)(slab % 3) * STAGE_BYTES;
#pragma unroll
        for (int kk = 0; kk < 4; kk++) {         // four k16 steps per slab
            const uint32_t kcol = kk * 32;
            uint32_t a_hi[4][4], b_hi[2][4];
#pragma unroll
            for (int mi = 0; mi < 4; mi++) {
                const uint32_t ar = st + swz((uint32_t)(a_row + mi * 16), kcol + a_coff);
                ldm_x4(a_hi[mi], sbase + OFF_AHI + ar);
            }
#pragma unroll
            for (int p = 0; p < 2; p++) {        // nj pairs {0,1}, {2,3}
                const uint32_t br = st + swz((uint32_t)(b_row + p * 16), kcol + b_coff);
                ldm_x4(b_hi[p], sbase + OFF_BHI + br);
            }
#pragma unroll
            for (int mi = 0; mi < 4; mi++)
#pragma unroll
                for (int nj = 0; nj < 4; nj++)
                    mma_f16(acc[mi][nj], a_hi[mi], &b_hi[nj >> 1][(nj & 1) * 2]);
        }
    }

    // ---------------- epilogue ----------------
    // c-frag layout: c0,c1 -> row lane/4, cols (lane%4)*2+{0,1}; c2,c3 -> row+8
    const int er0 = rowA0 + warp_m * 64 + (lane >> 2);
    const int ec0 = rowB0 + warp_n * 32 + (lane & 3) * 2;

    if (MODE == 2) {
        __syncthreads();                          // mainloop smem reuse
        float* sm_dot = (float*)smem;             // [128 rows][4 warp_n]
#pragma unroll
        for (int mi = 0; mi < 4; mi++) {
#pragma unroll
            for (int half = 0; half < 2; half++) {
                const int row = er0 + mi * 16 + half * 8;
                float rs = 0.0f;
#pragma unroll
                for (int nj = 0; nj < 4; nj++) {
                    const int col = ec0 + nj * 8;
                    float2 v;
                    v.x = acc[mi][nj][half * 2 + 0];
                    v.y = acc[mi][nj][half * 2 + 1];
                    const size_t o = (size_t)row * Ktot + col;
                    const float ax = __half2float(Ahi[o]);
                    const float ay = __half2float(Ahi[o + 1]);
                    rs = fmaf(ax, v.x, rs);
                    rs = fmaf(ay, v.y, rs);
                    if (row < DIM_K) {            // write U (fp16 hi only)
                        __half2 h2;
                        h2.x = __float2half_rn(v.x);
                        h2.y = __float2half_rn(v.y);
                        *(__half2*)(Uhi + (size_t)row * DIM_D + col) = h2;
                    }
                }
                rs += __shfl_xor_sync(0xFFFFFFFFu, rs, 1);
                rs += __shfl_xor_sync(0xFFFFFFFFu, rs, 2);
                if ((lane & 3) == 0) {
                    const int lr = warp_m * 64 + mi * 16 + half * 8 + (lane >> 2);
                    sm_dot[lr * 4 + warp_n] = rs;
                }
            }
        }
        __syncthreads();
        if (tid < 128) {
            const float s = sm_dot[tid * 4] + sm_dot[tid * 4 + 1]
                          + sm_dot[tid * 4 + 2] + sm_dot[tid * 4 + 3];
            dotp[(size_t)blockIdx.x * DIM_CM + rowA0 + tid] = s;
        }
        return;
    }

#pragma unroll
    for (int mi = 0; mi < 4; mi++) {
#pragma unroll
        for (int half = 0; half < 2; half++) {
            const int row = er0 + mi * 16 + half * 8;
            float radd = 0.0f;
            if (MODE == 1) radd = rowAdd[row];
#pragma unroll
            for (int nj = 0; nj < 4; nj++) {
                const int col = ec0 + nj * 8;
                float2 v;
                v.x = acc[mi][nj][half * 2 + 0];
                v.y = acc[mi][nj][half * 2 + 1];
                if (MODE == 1) {
                    const float2 ca = *(const float2*)(colAdd + col);
                    v.x = sqrtf(fmaxf(ca.x - 2.0f * v.x + radd, 0.0f));
                    v.y = sqrtf(fmaxf(ca.y - 2.0f * v.y + radd, 0.0f));
                }
                *(float2*)(Cout + (size_t)row * No + col) = v;
            }
        }
    }
}

// ------------------------- fused conversion kernel --------------------------
// One launch handles all three input transforms via block-range dispatch:
//   blocks [0, 4096)            : C   [2048,512] fp32 -> CM_hi rows [0,2048)
//   blocks [4096, 4096+2048)    : X   [4096,512] -> Xt_hi [512,4096] (transpose)
//   blocks [6144, 6144+2048)    : M   [512,4096] -> Mt_hi [4096,512] (transpose)
__global__ void convert_all_kernel(const float* __restrict__ X,
                                   const float* __restrict__ M,
                                   const float* __restrict__ C,
                                   __half* __restrict__ Xt_hi,
                                   __half* __restrict__ CM_hi)
{
    const int b = blockIdx.x;
    if (b < 4096) {
        // C convert: 4096 blocks x 256 elements
        const int i = b * 256 + threadIdx.x;
        CM_hi[i] = __float2half_rn(C[i]);
        return;
    }
    __shared__ float t[32][33];
    const int tx = threadIdx.x & 31;
    const int ty = threadIdx.x >> 5;   // 0..7
    if (b < 6144) {
        // X transpose: tile grid (16, 128): bx in [0,16) over D, by over N
        const int tb = b - 4096;
        const int bx = tb & 15;          // D / 32
        const int by = tb >> 4;          // N / 32
        const int x = bx * 32 + tx;
        const int y0 = by * 32;
#pragma unroll
        for (int j = 0; j < 32; j += 8)
            t[ty + j][tx] = X[(size_t)(y0 + ty + j) * DIM_D + x];
        __syncthreads();
#pragma unroll
        for (int j = 0; j < 32; j += 8) {
            const int c = bx * 32 + ty + j;   // out row (= D index)
            const int r = y0 + tx;            // out col (= N index)
            Xt_hi[(size_t)c * DIM_N + r] = __float2half_rn(t[tx][ty + j]);
        }
    } else {
        // M transpose: tile grid (128, 16): bx over M-cols, by over D
        const int tb = b - 6144;
        const int bx = tb & 127;         // M / 32
        const int by = tb >> 7;          // D / 32
        const int x = bx * 32 + tx;
        const int y0 = by * 32;
#pragma unroll
        for (int j = 0; j < 32; j += 8)
            t[ty + j][tx] = M[(size_t)(y0 + ty + j) * DIM_M + x];
        __syncthreads();
#pragma unroll
        for (int j = 0; j < 32; j += 8) {
            const int c = bx * 32 + ty + j;   // out row (= M index)
            const int r = y0 + tx;            // out col (= D index)
            CM_hi[(size_t)(DIM_K + c) * DIM_D + r] = __float2half_rn(t[tx][ty + j]);
        }
    }
}

// sum split-K partials of S -> fp16 hi
__global__ void reduce_split_kernel(const float* __restrict__ part,
                                    __half* __restrict__ hi, int n)
{
    const int i = blockIdx.x * blockDim.x + threadIdx.x;
    if (i >= n) return;
    float acc = 0.0f;
#pragma unroll
    for (int z = 0; z < ZSPLIT; z++) acc += part[i + (size_t)z * n];
    hi[i] = __float2half_rn(acc);
}

__global__ void combine_dots_kernel(const float* __restrict__ dotp,
                                    float* __restrict__ xc2, float* __restrict__ xm2)
{
    const int i = blockIdx.x * blockDim.x + threadIdx.x;
    if (i >= DIM_CM) return;
    const float s = dotp[i] + dotp[DIM_CM + i] + dotp[2 * DIM_CM + i] + dotp[3 * DIM_CM + i];
    if (i < DIM_K) xc2[i] = s;
    else           xm2[i - DIM_K] = s;
}

// --------------------------------- launch ----------------------------------
extern "C" void kernel_launch(void* const* d_in, const int* in_sizes, int n_in,
                              void* d_out, int out_size)
{
    const float* X = (const float*)d_in[0];  // [4096, 512]
    const float* M = (const float*)d_in[1];  // [512, 4096]
    const float* C = (const float*)d_in[2];  // [2048, 512]
    float* out = (float*)d_out;              // [2048, 4096]

    static bool attr_done = false;
    if (!attr_done) {
        cudaFuncSetAttribute(f16s_gemm<0>, cudaFuncAttributeMaxDynamicSharedMemorySize, GEMM_SMEM);
        cudaFuncSetAttribute(f16s_gemm<1>, cudaFuncAttributeMaxDynamicSharedMemorySize, GEMM_SMEM);
        cudaFuncSetAttribute(f16s_gemm<2>, cudaFuncAttributeMaxDynamicSharedMemorySize, GEMM_SMEM);
        attr_done = true;
    }

    __half *Xt_hi, *CM_hi, *S_hi, *U_hi;
    float *Spart, *dotp, *xm2, *xc2;
    cudaGetSymbolAddress((void**)&Xt_hi, g_Xt_hi);
    cudaGetSymbolAddress((void**)&CM_hi, g_CM_hi);
    cudaGetSymbolAddress((void**)&S_hi,  g_S_hi);
    cudaGetSymbolAddress((void**)&U_hi,  g_U_hi);
    cudaGetSymbolAddress((void**)&Spart, g_Spart);
    cudaGetSymbolAddress((void**)&dotp,  g_dotp);
    cudaGetSymbolAddress((void**)&xm2,   g_xm2);
    cudaGetSymbolAddress((void**)&xc2,   g_xc2);

    __half* Mt_hi = CM_hi + (size_t)DIM_K * DIM_D;  // rows 2048..6143

    // 1) fused conversions: C -> CM_hi[0:2048), X -> Xt_hi, M -> Mt_hi
    convert_all_kernel<<<4096 + 2048 + 2048, 256>>>(X, M, C, Xt_hi, CM_hi);

    // 2) S = Xt_hi @ Xt_hi^T  [512,512], K=4096, split-K=8 (8 slabs each)
    f16s_gemm<0><<<dim3(DIM_D / 128, DIM_D / 128, ZSPLIT), 256, GEMM_SMEM>>>(
        Xt_hi, Xt_hi, Spart,
        DIM_D, DIM_N, DIM_N / ZSPLIT, (size_t)DIM_D * DIM_D,
        nullptr, nullptr, nullptr, nullptr);
    reduce_split_kernel<<<(DIM_D * DIM_D) / 256, 256>>>(Spart, S_hi, DIM_D * DIM_D);

    // 3) UT = CM_hi @ S_hi  (MODE2: writes U_hi for C rows + dot partials)
    f16s_gemm<2><<<dim3(DIM_D / 128, DIM_CM / 128, 1), 256, GEMM_SMEM>>>(
        CM_hi, S_hi, nullptr, DIM_D, DIM_D, DIM_D, 0,
        nullptr, nullptr, U_hi, dotp);

    // 4) xc2[k] = c_k^T S c_k ; xm2[m] = m^T S m
    combine_dots_kernel<<<(DIM_CM + 255) / 256, 256>>>(dotp, xc2, xm2);

    // 5) out[k,m] = sqrt(max(xm2[m] - 2*(U_hi @ Mt_hi^T)[k,m] + xc2[k], 0))
    f16s_gemm<1><<<dim3(DIM_M / 128, DIM_K / 128, 1), 256, GEMM_SMEM>>>(
        U_hi, Mt_hi, out, DIM_M, DIM_D, DIM_D, 0,
        xc2, xm2, nullptr, nullptr);
}